// round 12
// baseline (speedup 1.0000x reference)
#include <cuda_runtime.h>
#include <math.h>

// ---------------------------------------------------------------------------
// Problem constants
// ---------------------------------------------------------------------------
constexpr int NN  = 30000;    // nodes per type
constexpr int NE  = 400000;   // edges per relation
constexpr int NR  = 10;       // relations
constexpr int NT  = 4;        // node types
constexpr int C1  = 128;      // layer1 channels
constexpr int H1  = 8;        // layer1 heads
constexpr int IN1 = 256;      // layer1 input dim
constexpr int C2  = 32;       // layer2 channels

__constant__ int c_SRC[NR]    = {0,1,2,3,0,1,2,1,3,1};
__constant__ int c_DST[NR]    = {0,1,2,3,1,0,1,2,1,3};
__constant__ int c_GRPOFF[5]  = {0,2,6,8,10};
__constant__ int c_GRP[NR]    = {0,5, 1,4,6,8, 2,7, 3,9};

// ---------------------------------------------------------------------------
// Scratch (static device arrays: allocation-free)
// ---------------------------------------------------------------------------
__device__ __align__(16) float g_h1   [NT*NN*C1];
__device__ __align__(16) float g_asrc1[NR*NN*H1];
__device__ __align__(16) float g_adst1[NR*NN*H1];
__device__ __align__(16) float g_out1 [NR*NN*C1];
__device__ __align__(16) float g_x2   [NT*NN*C1];
__device__ __align__(16) float g_h2   [NT*NN*C2];
__device__ __align__(16) float g_asrc2[NR*NN];
__device__ __align__(16) float g_adst2[NR*NN];
__device__ __align__(16) float g_out2 [NR*NN*C2];
__device__ float g_colsum1[NR*C1];
__device__ float g_colsum2[NR*C2];
__device__ float g_sattn1[NR];
__device__ float g_sattn2[NR];
__device__ int   g_counts [NR*NN];
__device__ int   g_offsets[NR*(NN+1)];
__device__ int   g_cursor [NR*NN];
__device__ int   g_srcs   [NR*NE];

// ---------------------------------------------------------------------------
// Packed f32x2 helpers (FFMA2)
// ---------------------------------------------------------------------------
__device__ __forceinline__ void ffma2(unsigned long long& c,
                                      unsigned long long a,
                                      unsigned long long b) {
    asm("fma.rn.f32x2 %0, %1, %2, %0;" : "+l"(c) : "l"(a), "l"(b));
}
__device__ __forceinline__ unsigned long long pk2(float x, float y) {
    unsigned long long r;
    asm("mov.b64 %0, {%1, %2};" : "=l"(r) : "f"(x), "f"(y));
    return r;
}
__device__ __forceinline__ float2 upk(unsigned long long v) {
    float2 r;
    asm("mov.b64 {%0, %1}, %2;" : "=f"(r.x), "=f"(r.y) : "l"(v));
    return r;
}

// ---------------------------------------------------------------------------
// Zeroing
// ---------------------------------------------------------------------------
__global__ void k_zero() {
    int i = blockIdx.x * blockDim.x + threadIdx.x;
    if (i < NR*NN) g_counts[i] = 0;
    if (i < NR*C1) g_colsum1[i] = 0.f;
    if (i < NR*C2) g_colsum2[i] = 0.f;
}

// ---------------------------------------------------------------------------
// CSR scan: one block (1024 threads) per relation
// ---------------------------------------------------------------------------
__global__ void k_scan() {
    const int e = blockIdx.x;
    const int t = threadIdx.x;
    constexpr int CH = 30;
    int base = t * CH;
    int cnt[CH];
    int sum = 0;
#pragma unroll
    for (int i = 0; i < CH; i++) {
        int idx = base + i;
        int v = (idx < NN) ? g_counts[e*NN + idx] : 0;
        cnt[i] = v; sum += v;
    }
    __shared__ int s[1024];
    s[t] = sum; __syncthreads();
    for (int d = 1; d < 1024; d <<= 1) {
        int v = (t >= d) ? s[t-d] : 0;
        __syncthreads();
        s[t] += v;
        __syncthreads();
    }
    int run = s[t] - sum;
#pragma unroll
    for (int i = 0; i < CH; i++) {
        int idx = base + i;
        if (idx < NN) {
            g_offsets[e*(NN+1) + idx] = run;
            g_cursor [e*NN + idx]     = run;
            run += cnt[i];
        }
    }
    if (t == 1023) g_offsets[e*(NN+1) + NN] = s[1023];
}

// ---------------------------------------------------------------------------
// fp32 GEMM (FFMA2 mainloop, m-pair accumulators: A feeds packed 64-bit pairs
// with zero packing MOVs; only B needs dup-packs). Double-buffered smem.
// BN=128: thread covers 8m x 8n (warps 2x4, threads 8x4).
// BN=32 : thread covers 8m x 2n (threads 16x16).
// MODE 0: C = acc + bias.  MODE 1: colsum[col] += sum_rows tanh(acc + bias).
// Fusion: blocks with blockIdx.x >= gemmGridX (z==0) run CSR edge counting.
// ---------------------------------------------------------------------------
template <int BN, int MODE>
__global__ void __launch_bounds__(256)
k_gemm(const float* __restrict__ A0, const float* __restrict__ A1,
       const float* __restrict__ A2, const float* __restrict__ A3,
       const float* __restrict__ B,
       const float* __restrict__ bias, float* __restrict__ C,
       int M, int Ncols, int K, long strideA, long strideB, long strideBias,
       long strideC, float* __restrict__ colsum, int colsumStride,
       int gemmGridX, const int* __restrict__ cEdges)
{
    constexpr int BM = 128, BK = 16;
    constexpr int NS = (BN == 128) ? 8 : 2;     // n singles per thread
    __shared__ float As[2][BK][BM];
    __shared__ float Bs[2][BK][BN];
    __shared__ float cs[BN];

    // ---- fused count role ----
    if ((int)blockIdx.x >= gemmGridX) {
        if (blockIdx.z != 0 || cEdges == nullptr) return;
        int nb = gridDim.x - gemmGridX;
        long base   = (long)((int)blockIdx.x - gemmGridX) * blockDim.x + threadIdx.x;
        long stride = (long)nb * blockDim.x;
        for (long idx = base; idx < (long)NR*NE; idx += stride) {
            int e = (int)(idx / NE), i = (int)(idx - (long)e*NE);
            int col = cEdges[(long)e*2*NE + NE + i];
            atomicAdd(&g_counts[e*NN + col], 1);
        }
        return;
    }

    const int z = blockIdx.z;
    const float* A = strideA ? (A0 + (long)z * strideA)
                             : (z == 0 ? A0 : z == 1 ? A1 : z == 2 ? A2 : A3);
    B    += (long)z * strideB;
    bias += (long)z * strideBias;
    if (MODE == 0) C += (long)z * strideC;

    const int m0 = blockIdx.x * BM;
    const int tid  = threadIdx.x;
    int mBase, nBase;
    if (BN == 128) {
        const int wid  = tid >> 5, lane = tid & 31;
        mBase = (wid >> 2)*64 + (lane >> 2)*8;
        nBase = (wid & 3)*32 + (lane & 3)*8;
    } else {
        mBase = (tid >> 4) * 8;
        nBase = (tid & 15) * 2;
    }

    // acc2[p][j]: lo = (m = mBase+2p, col nBase+j), hi = (m = mBase+2p+1, col nBase+j)
    unsigned long long acc2[4][NS];
#pragma unroll
    for (int p = 0; p < 4; p++)
#pragma unroll
        for (int j = 0; j < NS; j++) acc2[p][j] = 0ull;

    const int am = tid >> 1, akq = (tid & 1) * 2;   // A: row, float4-pair idx
    const float4 zero4 = make_float4(0.f,0.f,0.f,0.f);
    float4 pa[2], pb[2];

    auto loadA = [&](int k0) {
        pa[0] = zero4; pa[1] = zero4;
        if (m0 + am < M) {
            const float4* src = reinterpret_cast<const float4*>(
                A + (long)(m0 + am)*K + k0 + akq*4);
            pa[0] = src[0]; pa[1] = src[1];
        }
    };
    auto loadB = [&](int k0) {
        if (BN == 128) {
#pragma unroll
            for (int it = 0; it < 2; it++) {
                int lin = tid + it * 256;
                int k = lin >> 5, nq = lin & 31;
                pb[it] = zero4;
                if (nq*4 + 3 < Ncols)
                    pb[it] = *reinterpret_cast<const float4*>(
                        B + (long)(k0+k)*Ncols + nq*4);
            }
        } else {
            if (tid < 128) {
                int k = tid >> 3, nq = tid & 7;
                pb[0] = zero4;
                if (nq*4 + 3 < Ncols)
                    pb[0] = *reinterpret_cast<const float4*>(
                        B + (long)(k0+k)*Ncols + nq*4);
            }
        }
    };
    auto storeT = [&](int buf) {
        As[buf][akq*4+0][am] = pa[0].x; As[buf][akq*4+1][am] = pa[0].y;
        As[buf][akq*4+2][am] = pa[0].z; As[buf][akq*4+3][am] = pa[0].w;
        As[buf][akq*4+4][am] = pa[1].x; As[buf][akq*4+5][am] = pa[1].y;
        As[buf][akq*4+6][am] = pa[1].z; As[buf][akq*4+7][am] = pa[1].w;
        if (BN == 128) {
#pragma unroll
            for (int it = 0; it < 2; it++) {
                int lin = tid + it * 256;
                int k = lin >> 5, nq = lin & 31;
                *reinterpret_cast<float4*>(&Bs[buf][k][nq*4]) = pb[it];
            }
        } else {
            if (tid < 128) {
                int k = tid >> 3, nq = tid & 7;
                *reinterpret_cast<float4*>(&Bs[buf][k][nq*4]) = pb[0];
            }
        }
    };

    const int nT = K / BK;
    loadA(0); loadB(0);
    storeT(0);
    __syncthreads();

    for (int t = 0; t < nT; t++) {
        int cur = t & 1;
        if (t + 1 < nT) { loadA((t+1)*BK); loadB((t+1)*BK); }
#pragma unroll
        for (int k = 0; k < BK; k++) {
            const unsigned long long* ap =
                reinterpret_cast<const unsigned long long*>(&As[cur][k][mBase]);
            unsigned long long a2[4] = {ap[0], ap[1], ap[2], ap[3]};
            unsigned long long b2[NS];
            if (BN == 128) {
                const float4* bp4 = reinterpret_cast<const float4*>(&Bs[cur][k][nBase]);
                float4 bv0 = bp4[0], bv1 = bp4[1];
                b2[0] = pk2(bv0.x, bv0.x); b2[1] = pk2(bv0.y, bv0.y);
                b2[2] = pk2(bv0.z, bv0.z); b2[3] = pk2(bv0.w, bv0.w);
                b2[4 % NS] = pk2(bv1.x, bv1.x); b2[5 % NS] = pk2(bv1.y, bv1.y);
                b2[6 % NS] = pk2(bv1.z, bv1.z); b2[7 % NS] = pk2(bv1.w, bv1.w);
            } else {
                float2 bv = *reinterpret_cast<const float2*>(&Bs[cur][k][nBase]);
                b2[0] = pk2(bv.x, bv.x);
                b2[1 % NS] = pk2(bv.y, bv.y);
            }
#pragma unroll
            for (int p = 0; p < 4; p++)
#pragma unroll
                for (int j = 0; j < NS; j++) ffma2(acc2[p][j], a2[p], b2[j]);
        }
        if (t + 1 < nT) storeT(1 - cur);
        __syncthreads();
    }

    if (MODE == 0) {
#pragma unroll
        for (int p = 0; p < 4; p++) {
            int r0 = m0 + mBase + 2*p;
            int r1 = r0 + 1;
            float lo[NS], hi[NS];
#pragma unroll
            for (int j = 0; j < NS; j++) {
                float2 v = upk(acc2[p][j]);
                lo[j] = v.x; hi[j] = v.y;
            }
#pragma unroll
            for (int j = 0; j < NS; j += 2) {
                int c = nBase + j;
                if (c + 1 < Ncols) {
                    float b0 = bias[c], b1 = bias[c+1];
                    if (r0 < M) {
                        float2 v; v.x = lo[j] + b0; v.y = lo[j+1] + b1;
                        *reinterpret_cast<float2*>(&C[(long)r0*Ncols + c]) = v;
                    }
                    if (r1 < M) {
                        float2 v; v.x = hi[j] + b0; v.y = hi[j+1] + b1;
                        *reinterpret_cast<float2*>(&C[(long)r1*Ncols + c]) = v;
                    }
                } else if (c < Ncols) {
                    float b0 = bias[c];
                    if (r0 < M) C[(long)r0*Ncols + c] = lo[j] + b0;
                    if (r1 < M) C[(long)r1*Ncols + c] = hi[j] + b0;
                }
            }
        }
    } else {
        if (tid < BN) cs[tid] = 0.f;
        __syncthreads();
#pragma unroll
        for (int j = 0; j < NS; j++) {
            int c = nBase + j;
            if (c < Ncols) {
                float b0 = bias[c];
                float s0 = 0.f;
#pragma unroll
                for (int p = 0; p < 4; p++) {
                    int r0 = m0 + mBase + 2*p;
                    float2 v = upk(acc2[p][j]);
                    if (r0 < M)     s0 += tanhf(v.x + b0);
                    if (r0 + 1 < M) s0 += tanhf(v.y + b0);
                }
                atomicAdd(&cs[c], s0);
            }
        }
        __syncthreads();
        if (tid < BN && tid < Ncols)
            atomicAdd(&colsum[z*colsumStride + tid], cs[tid]);
    }
}

// ---------------------------------------------------------------------------
// Attention logits, layer 1: warp per (relation, node).
// Fusion: blocks with blockIdx.x >= gx (y==0) run CSR fill (grid-stride).
// ---------------------------------------------------------------------------
__global__ void k_logits1(const float* __restrict__ att_src,
                          const float* __restrict__ att_dst,
                          int gx, const int* __restrict__ fEdges)
{
    if ((int)blockIdx.x >= gx) {
        if (blockIdx.y != 0 || fEdges == nullptr) return;
        int nb = gridDim.x - gx;
        long base   = (long)((int)blockIdx.x - gx) * blockDim.x + threadIdx.x;
        long stride = (long)nb * blockDim.x;
        for (long idx = base; idx < (long)NR*NE; idx += stride) {
            int e = (int)(idx / NE), i = (int)(idx - (long)e*NE);
            int row = fEdges[(long)e*2*NE + i];
            int col = fEdges[(long)e*2*NE + NE + i];
            int pos = atomicAdd(&g_cursor[e*NN + col], 1);
            g_srcs[e*NE + pos] = row;
        }
        return;
    }

    int e = blockIdx.y;
    int n = blockIdx.x * 8 + (threadIdx.x >> 5);
    if (n >= NN) return;
    int l = threadIdx.x & 31;

    const float4* hs = reinterpret_cast<const float4*>(g_h1 + c_SRC[e]*NN*C1 + n*C1);
    const float4* hd = reinterpret_cast<const float4*>(g_h1 + c_DST[e]*NN*C1 + n*C1);
    const float4* as = reinterpret_cast<const float4*>(att_src + e*C1);
    const float4* ad = reinterpret_cast<const float4*>(att_dst + e*C1);

    float4 a = hs[l], b = as[l];
    float ps = a.x*b.x + a.y*b.y + a.z*b.z + a.w*b.w;
    float4 c = hd[l], d = ad[l];
    float pd = c.x*d.x + c.y*d.y + c.z*d.z + c.w*d.w;
    ps += __shfl_xor_sync(0xffffffffu, ps, 1);
    ps += __shfl_xor_sync(0xffffffffu, ps, 2);
    pd += __shfl_xor_sync(0xffffffffu, pd, 1);
    pd += __shfl_xor_sync(0xffffffffu, pd, 2);
    if ((l & 3) == 0) {
        g_asrc1[(e*NN + n)*H1 + (l >> 2)] = ps;
        g_adst1[(e*NN + n)*H1 + (l >> 2)] = pd;
    }
}

// ---------------------------------------------------------------------------
// Aggregation layer 1 (fused segment softmax): warp per (node, relation).
// Pass A computes per-head (m, 1/s) online (4 lanes/head, merged via shfl);
// Pass B gathers rows with inline-recomputed weights. No soft kernel needed.
// ---------------------------------------------------------------------------
__global__ void k_agg1() {
    int e = blockIdx.y;
    int n = blockIdx.x * 8 + (threadIdx.x >> 5);
    if (n >= NN) return;
    int l  = threadIdx.x & 31;
    int h  = l >> 2;
    int il = l & 3;

    int off = g_offsets[e*(NN+1) + n];
    int deg = g_offsets[e*(NN+1) + n + 1] - off;
    float4* out = reinterpret_cast<float4*>(g_out1 + (long)(e*NN + n) * C1);
    if (deg == 0) { out[l] = make_float4(0.f,0.f,0.f,0.f); return; }

    const int*    sr  = g_srcs + e*NE + off;
    const float*  asr = g_asrc1 + e*NN*H1;
    const float4* hs  = reinterpret_cast<const float4*>(g_h1 + c_SRC[e]*NN*C1);
    float ad = g_adst1[(e*NN + n)*H1 + h];

    // ---- pass A: online (m, s) per head ----
    float m = -1e30f, s = 0.f;
    for (int i = il; i < deg; i += 4) {
        float a = asr[sr[i]*H1 + h] + ad;
        a = a > 0.f ? a : 0.2f * a;
        if (a > m) { s = s * __expf(m - a) + 1.f; m = a; }
        else        s += __expf(a - m);
    }
#pragma unroll
    for (int o = 1; o <= 2; o <<= 1) {
        float mo = __shfl_xor_sync(0xffffffffu, m, o);
        float so = __shfl_xor_sync(0xffffffffu, s, o);
        float mn = fmaxf(m, mo);
        s = s * __expf(m - mn) + so * __expf(mo - mn);
        m = mn;
    }
    float inv = 1.f / (s + 1e-16f);

    // ---- pass B: weighted gather ----
    float4 acc = make_float4(0.f,0.f,0.f,0.f);
    int i = 0;
    for (; i + 4 <= deg; i += 4) {
        int r0 = sr[i], r1 = sr[i+1], r2 = sr[i+2], r3 = sr[i+3];
        float a0 = asr[r0*H1 + h] + ad, a1 = asr[r1*H1 + h] + ad;
        float a2 = asr[r2*H1 + h] + ad, a3 = asr[r3*H1 + h] + ad;
        a0 = a0 > 0.f ? a0 : 0.2f*a0;  a1 = a1 > 0.f ? a1 : 0.2f*a1;
        a2 = a2 > 0.f ? a2 : 0.2f*a2;  a3 = a3 > 0.f ? a3 : 0.2f*a3;
        float w0 = __expf(a0 - m) * inv, w1 = __expf(a1 - m) * inv;
        float w2 = __expf(a2 - m) * inv, w3 = __expf(a3 - m) * inv;
        float4 v0 = hs[r0*32 + l], v1 = hs[r1*32 + l];
        float4 v2 = hs[r2*32 + l], v3 = hs[r3*32 + l];
        acc.x += w0*v0.x + w1*v1.x + w2*v2.x + w3*v3.x;
        acc.y += w0*v0.y + w1*v1.y + w2*v2.y + w3*v3.y;
        acc.z += w0*v0.z + w1*v1.z + w2*v2.z + w3*v3.z;
        acc.w += w0*v0.w + w1*v1.w + w2*v2.w + w3*v3.w;
    }
    for (; i < deg; i++) {
        int r = sr[i];
        float a = asr[r*H1 + h] + ad;
        a = a > 0.f ? a : 0.2f*a;
        float wv = __expf(a - m) * inv;
        float4 v = hs[r*32 + l];
        acc.x += wv*v.x; acc.y += wv*v.y; acc.z += wv*v.z; acc.w += wv*v.w;
    }
    out[l] = make_float4(fmaxf(acc.x,0.f), fmaxf(acc.y,0.f),
                         fmaxf(acc.z,0.f), fmaxf(acc.w,0.f));
}

// ---------------------------------------------------------------------------
// Semantic score + group softmax (tiny)
// ---------------------------------------------------------------------------
__global__ void k_score1(const float* __restrict__ q) {
    __shared__ float red[128];
    __shared__ float sc[NR];
    int t = threadIdx.x;
    for (int e = 0; e < NR; e++) {
        float p = q[t] * g_colsum1[e*C1 + t];
        red[t] = p; __syncthreads();
        for (int s = 64; s > 0; s >>= 1) {
            if (t < s) red[t] += red[t + s];
            __syncthreads();
        }
        if (t == 0) sc[e] = red[0] / (float)NN;
        __syncthreads();
    }
    if (t < NT) {
        int b = c_GRPOFF[t], e2 = c_GRPOFF[t+1];
        float m = -1e30f;
        for (int g = b; g < e2; g++) m = fmaxf(m, sc[c_GRP[g]]);
        float ssum = 0.f;
        for (int g = b; g < e2; g++) ssum += expf(sc[c_GRP[g]] - m);
        for (int g = b; g < e2; g++)
            g_sattn1[c_GRP[g]] = expf(sc[c_GRP[g]] - m) / ssum;
    }
}

__global__ void k_score2(const float* __restrict__ q) {
    __shared__ float red[128];
    __shared__ float sc[NR];
    int t = threadIdx.x;
    for (int e = 0; e < NR; e++) {
        float p = (t < C2) ? q[t] * g_colsum2[e*C2 + t] : 0.f;
        red[t] = p; __syncthreads();
        for (int s = 64; s > 0; s >>= 1) {
            if (t < s) red[t] += red[t + s];
            __syncthreads();
        }
        if (t == 0) sc[e] = red[0] / (float)NN;
        __syncthreads();
    }
    if (t < NT) {
        int b = c_GRPOFF[t], e2 = c_GRPOFF[t+1];
        float m = -1e30f;
        for (int g = b; g < e2; g++) m = fmaxf(m, sc[c_GRP[g]]);
        float ssum = 0.f;
        for (int g = b; g < e2; g++) ssum += expf(sc[c_GRP[g]] - m);
        for (int g = b; g < e2; g++)
            g_sattn2[c_GRP[g]] = expf(sc[c_GRP[g]] - m) / ssum;
    }
}

// ---------------------------------------------------------------------------
// Fuse relations per dst type (layer1) + elu -> x2
// ---------------------------------------------------------------------------
__global__ void k_combine1() {
    long idx = (long)blockIdx.x * blockDim.x + threadIdx.x;
    if (idx >= (long)NT*NN*C1) return;
    int t  = (int)(idx / (NN*C1));
    int nc = (int)(idx - (long)t*NN*C1);
    float v = 0.f;
    for (int g = c_GRPOFF[t]; g < c_GRPOFF[t+1]; g++) {
        int e = c_GRP[g];
        v += g_sattn1[e] * g_out1[(long)e*NN*C1 + nc];
    }
    g_x2[idx] = v > 0.f ? v : __expf(v) - 1.f;
}

// ---------------------------------------------------------------------------
// Layer 2 logits (H=1): warp per (relation, node)
// ---------------------------------------------------------------------------
__global__ void k_logits2(const float* __restrict__ att_src,
                          const float* __restrict__ att_dst)
{
    int e = blockIdx.y;
    int n = blockIdx.x * 8 + (threadIdx.x >> 5);
    if (n >= NN) return;
    int l = threadIdx.x & 31;
    float ps = g_h2[c_SRC[e]*NN*C2 + n*C2 + l] * att_src[e*C2 + l];
    float pd = g_h2[c_DST[e]*NN*C2 + n*C2 + l] * att_dst[e*C2 + l];
#pragma unroll
    for (int o = 16; o > 0; o >>= 1) {
        ps += __shfl_xor_sync(0xffffffffu, ps, o);
        pd += __shfl_xor_sync(0xffffffffu, pd, o);
    }
    if (l == 0) { g_asrc2[e*NN + n] = ps; g_adst2[e*NN + n] = pd; }
}

// ---------------------------------------------------------------------------
// Aggregation layer 2 (fused segment softmax): warp per (node, relation).
// Pass A: full-warp online (m, s). Pass B: 4 edges in flight, 8 lanes each.
// ---------------------------------------------------------------------------
__global__ void k_agg2() {
    int e = blockIdx.y;
    int n = blockIdx.x * 8 + (threadIdx.x >> 5);
    if (n >= NN) return;
    int l = threadIdx.x & 31;
    int g = l >> 3;                    // edge group 0..3
    int q = l & 7;                     // channel quad 0..7

    int off = g_offsets[e*(NN+1) + n];
    int deg = g_offsets[e*(NN+1) + n + 1] - off;
    float4* out = reinterpret_cast<float4*>(g_out2 + (long)(e*NN + n) * C2);
    if (deg == 0) { if (l < 8) out[q] = make_float4(0.f,0.f,0.f,0.f); return; }

    const int*    sr  = g_srcs + e*NE + off;
    const float*  asr = g_asrc2 + e*NN;
    const float4* hs  = reinterpret_cast<const float4*>(g_h2 + c_SRC[e]*NN*C2);
    float ad = g_adst2[e*NN + n];

    // ---- pass A: online (m, s) across the whole warp ----
    float m = -1e30f, s = 0.f;
    for (int i = l; i < deg; i += 32) {
        float a = asr[sr[i]] + ad;
        a = a > 0.f ? a : 0.2f * a;
        if (a > m) { s = s * __expf(m - a) + 1.f; m = a; }
        else        s += __expf(a - m);
    }
#pragma unroll
    for (int o = 1; o <= 16; o <<= 1) {
        float mo = __shfl_xor_sync(0xffffffffu, m, o);
        float so = __shfl_xor_sync(0xffffffffu, s, o);
        float mn = fmaxf(m, mo);
        s = s * __expf(m - mn) + so * __expf(mo - mn);
        m = mn;
    }
    float inv = 1.f / (s + 1e-16f);

    // ---- pass B: weighted gather ----
    float4 acc = make_float4(0.f,0.f,0.f,0.f);
    for (int i = g; i < deg; i += 4) {
        int r = sr[i];
        float a = asr[r] + ad;
        a = a > 0.f ? a : 0.2f*a;
        float wv = __expf(a - m) * inv;
        float4 v = hs[r*8 + q];
        acc.x += wv*v.x; acc.y += wv*v.y; acc.z += wv*v.z; acc.w += wv*v.w;
    }
#pragma unroll
    for (int o = 8; o <= 16; o <<= 1) {
        acc.x += __shfl_xor_sync(0xffffffffu, acc.x, o);
        acc.y += __shfl_xor_sync(0xffffffffu, acc.y, o);
        acc.z += __shfl_xor_sync(0xffffffffu, acc.z, o);
        acc.w += __shfl_xor_sync(0xffffffffu, acc.w, o);
    }
    if (l < 8)
        out[q] = make_float4(fmaxf(acc.x,0.f), fmaxf(acc.y,0.f),
                             fmaxf(acc.z,0.f), fmaxf(acc.w,0.f));
}

// ---------------------------------------------------------------------------
// Fuse relations layer 2 + final per-node channel softmax -> d_out
// ---------------------------------------------------------------------------
__global__ void k_combine2(float* __restrict__ out) {
    int g = blockIdx.x * 8 + (threadIdx.x >> 5);
    if (g >= NT*NN) return;
    int t = g / NN, n = g - t*NN;
    int c = threadIdx.x & 31;
    float v = 0.f;
    for (int gi = c_GRPOFF[t]; gi < c_GRPOFF[t+1]; gi++) {
        int e = c_GRP[gi];
        v += g_sattn2[e] * g_out2[(long)(e*NN + n)*C2 + c];
    }
    float m = v;
#pragma unroll
    for (int o = 16; o > 0; o >>= 1)
        m = fmaxf(m, __shfl_xor_sync(0xffffffffu, m, o));
    float ex = __expf(v - m);
    float s = ex;
#pragma unroll
    for (int o = 16; o > 0; o >>= 1)
        s += __shfl_xor_sync(0xffffffffu, s, o);
    out[(long)g*C2 + c] = ex / s;
}

// ---------------------------------------------------------------------------
// Host launcher
// ---------------------------------------------------------------------------
extern "C" void kernel_launch(void* const* d_in, const int* in_sizes, int n_in,
                              void* d_out, int out_size)
{
    const float* x[4] = {(const float*)d_in[0], (const float*)d_in[1],
                         (const float*)d_in[2], (const float*)d_in[3]};
    const int*   edges    = (const int*)  d_in[4];
    const float* proj1_W  = (const float*)d_in[5];
    const float* proj1_b  = (const float*)d_in[6];
    const float* att1_src = (const float*)d_in[7];
    const float* att1_dst = (const float*)d_in[8];
    const float* k1_W     = (const float*)d_in[9];
    const float* k1_b     = (const float*)d_in[10];
    const float* q1       = (const float*)d_in[11];
    const float* proj2_W  = (const float*)d_in[12];
    const float* proj2_b  = (const float*)d_in[13];
    const float* att2_src = (const float*)d_in[14];
    const float* att2_dst = (const float*)d_in[15];
    const float* k2_W     = (const float*)d_in[16];
    const float* k2_b     = (const float*)d_in[17];
    const float* q2       = (const float*)d_in[18];
    float* out = (float*)d_out;

    float *h1p, *x2p, *h2p, *out1p, *out2p, *cs1p, *cs2p;
    cudaGetSymbolAddress((void**)&h1p,   g_h1);
    cudaGetSymbolAddress((void**)&x2p,   g_x2);
    cudaGetSymbolAddress((void**)&h2p,   g_h2);
    cudaGetSymbolAddress((void**)&out1p, g_out1);
    cudaGetSymbolAddress((void**)&out2p, g_out2);
    cudaGetSymbolAddress((void**)&cs1p,  g_colsum1);
    cudaGetSymbolAddress((void**)&cs2p,  g_colsum2);

    const int MT   = (NN + 127) / 128;   // 235 row tiles
    const int CNTB = 512;                // fused count blocks
    const int FILB = 512;                // fused fill blocks
    const int LGX  = (NN + 7) / 8;       // 3750

    k_zero <<<(NR*NN + 255)/256, 256>>>();

    // fused [proj1 GEMM ∥ count]
    k_gemm<128,0><<<dim3(MT + CNTB, 1, NT), 256>>>(
        x[0], x[1], x[2], x[3],
        proj1_W, proj1_b, h1p, NN, C1, IN1,
        0, (long)IN1*C1, C1, (long)NN*C1, nullptr, 0,
        MT, edges);

    k_scan <<<NR, 1024>>>();

    // fused [logits1 ∥ fill]
    k_logits1<<<dim3(LGX + FILB, NR), 256>>>(att1_src, att1_dst, LGX, edges);

    // fused [softmax + aggregation]
    k_agg1<<<dim3(LGX, NR), 256>>>();

    k_gemm<128,1><<<dim3(MT, 1, NR), 256>>>(
        out1p, nullptr, nullptr, nullptr,
        k1_W, k1_b, nullptr, NN, C1, C1,
        (long)NN*C1, 0, 0, 0, cs1p, C1,
        MT, nullptr);
    k_score1<<<1, 128>>>(q1);
    k_combine1<<<((long)NT*NN*C1 + 255)/256, 256>>>();

    // ---- layer 2 projections, batched z=4, BN=32 ----
    k_gemm<32,0><<<dim3(MT, 1, NT), 256>>>(
        x2p, nullptr, nullptr, nullptr,
        proj2_W, proj2_b, h2p, NN, C2, C1,
        (long)NN*C1, (long)C1*C2, C2, (long)NN*C2, nullptr, 0,
        MT, nullptr);

    k_logits2<<<dim3(LGX, NR), 256>>>(att2_src, att2_dst);
    k_agg2   <<<dim3(LGX, NR), 256>>>();

    k_gemm<32,1><<<dim3(MT, 1, NR), 256>>>(
        out2p, nullptr, nullptr, nullptr,
        k2_W, k2_b, nullptr, NN, C2, C2,
        (long)NN*C2, 0, 0, 0, cs2p, C2,
        MT, nullptr);
    k_score2<<<1, 128>>>(q2);

    k_combine2<<<(NT*NN + 7)/8, 256>>>(out);
}

// round 13
// speedup vs baseline: 1.0999x; 1.0999x over previous
#include <cuda_runtime.h>
#include <math.h>

// ---------------------------------------------------------------------------
// Problem constants
// ---------------------------------------------------------------------------
constexpr int NN  = 30000;    // nodes per type
constexpr int NE  = 400000;   // edges per relation
constexpr int NR  = 10;       // relations
constexpr int NT  = 4;        // node types
constexpr int C1  = 128;      // layer1 channels
constexpr int H1  = 8;        // layer1 heads
constexpr int IN1 = 256;      // layer1 input dim
constexpr int C2  = 32;       // layer2 channels

__constant__ int c_SRC[NR]    = {0,1,2,3,0,1,2,1,3,1};
__constant__ int c_DST[NR]    = {0,1,2,3,1,0,1,2,1,3};
__constant__ int c_GRPOFF[5]  = {0,2,6,8,10};
__constant__ int c_GRP[NR]    = {0,5, 1,4,6,8, 2,7, 3,9};

// ---------------------------------------------------------------------------
// Scratch (static device arrays: allocation-free)
// ---------------------------------------------------------------------------
__device__ __align__(16) float g_h1   [NT*NN*C1];
__device__ __align__(16) float g_asrc1[NR*NN*H1];
__device__ __align__(16) float g_adst1[NR*NN*H1];
__device__ __align__(16) float g_out1 [NR*NN*C1];
__device__ __align__(16) float g_x2   [NT*NN*C1];
__device__ __align__(16) float g_h2   [NT*NN*C2];
__device__ __align__(16) float g_asrc2[NR*NN];
__device__ __align__(16) float g_adst2[NR*NN];
__device__ __align__(16) float g_out2 [NR*NN*C2];
__device__ float g_colsum1[NR*C1];
__device__ float g_colsum2[NR*C2];
__device__ float g_sattn1[NR];
__device__ float g_sattn2[NR];
__device__ int   g_counts [NR*NN];
__device__ int   g_offsets[NR*(NN+1)];
__device__ int   g_cursor [NR*NN];
__device__ int   g_srcs   [NR*NE];

// ---------------------------------------------------------------------------
// Packed f32x2 helpers (FFMA2)
// ---------------------------------------------------------------------------
__device__ __forceinline__ void ffma2(unsigned long long& c,
                                      unsigned long long a,
                                      unsigned long long b) {
    asm("fma.rn.f32x2 %0, %1, %2, %0;" : "+l"(c) : "l"(a), "l"(b));
}
__device__ __forceinline__ unsigned long long pk2(float x, float y) {
    unsigned long long r;
    asm("mov.b64 %0, {%1, %2};" : "=l"(r) : "f"(x), "f"(y));
    return r;
}
__device__ __forceinline__ float2 upk(unsigned long long v) {
    float2 r;
    asm("mov.b64 {%0, %1}, %2;" : "=f"(r.x), "=f"(r.y) : "l"(v));
    return r;
}

// ---------------------------------------------------------------------------
// Zeroing
// ---------------------------------------------------------------------------
__global__ void k_zero() {
    int i = blockIdx.x * blockDim.x + threadIdx.x;
    if (i < NR*NN) g_counts[i] = 0;
    if (i < NR*C1) g_colsum1[i] = 0.f;
    if (i < NR*C2) g_colsum2[i] = 0.f;
}

// ---------------------------------------------------------------------------
// CSR scan: one block (1024 threads) per relation
// ---------------------------------------------------------------------------
__global__ void k_scan() {
    const int e = blockIdx.x;
    const int t = threadIdx.x;
    constexpr int CH = 30;
    int base = t * CH;
    int cnt[CH];
    int sum = 0;
#pragma unroll
    for (int i = 0; i < CH; i++) {
        int idx = base + i;
        int v = (idx < NN) ? g_counts[e*NN + idx] : 0;
        cnt[i] = v; sum += v;
    }
    __shared__ int s[1024];
    s[t] = sum; __syncthreads();
    for (int d = 1; d < 1024; d <<= 1) {
        int v = (t >= d) ? s[t-d] : 0;
        __syncthreads();
        s[t] += v;
        __syncthreads();
    }
    int run = s[t] - sum;
#pragma unroll
    for (int i = 0; i < CH; i++) {
        int idx = base + i;
        if (idx < NN) {
            g_offsets[e*(NN+1) + idx] = run;
            g_cursor [e*NN + idx]     = run;
            run += cnt[i];
        }
    }
    if (t == 1023) g_offsets[e*(NN+1) + NN] = s[1023];
}

// ---------------------------------------------------------------------------
// fp32 GEMM (FFMA2 mainloop, double-buffered smem, one sync per tile).
// R10-proven inner loop: n-pair f32x2 accumulators, float4 fragment LDS,
// a-broadcast packing.
// BN=128: 8x8 microtile, warps 2x4, threads 8x4 (m x n).
// BN=32 : 8x2 microtile, threads 16 (m) x 16 (n).
// MODE 0: C = acc + bias.  MODE 1: colsum[col] += sum_rows tanh(acc + bias).
// Fusion: blocks with blockIdx.x >= gemmGridX (z==0) run CSR edge counting.
// ---------------------------------------------------------------------------
template <int BN, int MODE>
__global__ void __launch_bounds__(256)
k_gemm(const float* __restrict__ A0, const float* __restrict__ A1,
       const float* __restrict__ A2, const float* __restrict__ A3,
       const float* __restrict__ B,
       const float* __restrict__ bias, float* __restrict__ C,
       int M, int Ncols, int K, long strideA, long strideB, long strideBias,
       long strideC, float* __restrict__ colsum, int colsumStride,
       int gemmGridX, const int* __restrict__ cEdges)
{
    constexpr int BM = 128, BK = 16;
    constexpr int NJ = (BN == 128) ? 4 : 1;
    __shared__ float As[2][BK][BM];
    __shared__ float Bs[2][BK][BN];
    __shared__ float cs[BN];

    // ---- fused count role ----
    if ((int)blockIdx.x >= gemmGridX) {
        if (blockIdx.z != 0 || cEdges == nullptr) return;
        int nb = gridDim.x - gemmGridX;
        long base   = (long)((int)blockIdx.x - gemmGridX) * blockDim.x + threadIdx.x;
        long stride = (long)nb * blockDim.x;
        for (long idx = base; idx < (long)NR*NE; idx += stride) {
            int e = (int)(idx / NE), i = (int)(idx - (long)e*NE);
            int col = cEdges[(long)e*2*NE + NE + i];
            atomicAdd(&g_counts[e*NN + col], 1);
        }
        return;
    }

    const int z = blockIdx.z;
    const float* A = strideA ? (A0 + (long)z * strideA)
                             : (z == 0 ? A0 : z == 1 ? A1 : z == 2 ? A2 : A3);
    B    += (long)z * strideB;
    bias += (long)z * strideBias;
    if (MODE == 0) C += (long)z * strideC;

    const int m0 = blockIdx.x * BM;
    const int tid  = threadIdx.x;
    int mBase, nBase;
    if (BN == 128) {
        const int wid  = tid >> 5, lane = tid & 31;
        mBase = (wid >> 2)*64 + (lane >> 2)*8;
        nBase = (wid & 3)*32 + (lane & 3)*8;
    } else {
        mBase = (tid >> 4) * 8;
        nBase = (tid & 15) * 2;
    }

    unsigned long long acc2[8][NJ];
#pragma unroll
    for (int i = 0; i < 8; i++)
#pragma unroll
        for (int j = 0; j < NJ; j++) acc2[i][j] = 0ull;

    const int am = tid >> 1, akq = (tid & 1) * 2;   // A: row, float4-pair idx
    const float4 zero4 = make_float4(0.f,0.f,0.f,0.f);
    float4 pa[2], pb[2];

    auto loadA = [&](int k0) {
        pa[0] = zero4; pa[1] = zero4;
        if (m0 + am < M) {
            const float4* src = reinterpret_cast<const float4*>(
                A + (long)(m0 + am)*K + k0 + akq*4);
            pa[0] = src[0]; pa[1] = src[1];
        }
    };
    auto loadB = [&](int k0) {
        if (BN == 128) {
#pragma unroll
            for (int it = 0; it < 2; it++) {
                int lin = tid + it * 256;
                int k = lin >> 5, nq = lin & 31;
                pb[it] = zero4;
                if (nq*4 + 3 < Ncols)
                    pb[it] = *reinterpret_cast<const float4*>(
                        B + (long)(k0+k)*Ncols + nq*4);
            }
        } else {
            if (tid < 128) {
                int k = tid >> 3, nq = tid & 7;
                pb[0] = zero4;
                if (nq*4 + 3 < Ncols)
                    pb[0] = *reinterpret_cast<const float4*>(
                        B + (long)(k0+k)*Ncols + nq*4);
            }
        }
    };
    auto storeT = [&](int buf) {
        As[buf][akq*4+0][am] = pa[0].x; As[buf][akq*4+1][am] = pa[0].y;
        As[buf][akq*4+2][am] = pa[0].z; As[buf][akq*4+3][am] = pa[0].w;
        As[buf][akq*4+4][am] = pa[1].x; As[buf][akq*4+5][am] = pa[1].y;
        As[buf][akq*4+6][am] = pa[1].z; As[buf][akq*4+7][am] = pa[1].w;
        if (BN == 128) {
#pragma unroll
            for (int it = 0; it < 2; it++) {
                int lin = tid + it * 256;
                int k = lin >> 5, nq = lin & 31;
                *reinterpret_cast<float4*>(&Bs[buf][k][nq*4]) = pb[it];
            }
        } else {
            if (tid < 128) {
                int k = tid >> 3, nq = tid & 7;
                *reinterpret_cast<float4*>(&Bs[buf][k][nq*4]) = pb[0];
            }
        }
    };

    const int nT = K / BK;
    loadA(0); loadB(0);
    storeT(0);
    __syncthreads();

    for (int t = 0; t < nT; t++) {
        int cur = t & 1;
        if (t + 1 < nT) { loadA((t+1)*BK); loadB((t+1)*BK); }
#pragma unroll
        for (int k = 0; k < BK; k++) {
            const float4* ap4 = reinterpret_cast<const float4*>(&As[cur][k][mBase]);
            float4 av0 = ap4[0], av1 = ap4[1];
            float a[8] = {av0.x, av0.y, av0.z, av0.w,
                          av1.x, av1.y, av1.z, av1.w};
            unsigned long long b2[NJ];
            if (BN == 128) {
                const float4* bp4 = reinterpret_cast<const float4*>(&Bs[cur][k][nBase]);
                float4 bv0 = bp4[0], bv1 = bp4[1];
                b2[0] = pk2(bv0.x, bv0.y);
                b2[1] = pk2(bv0.z, bv0.w);
                b2[2 % NJ] = pk2(bv1.x, bv1.y);
                b2[3 % NJ] = pk2(bv1.z, bv1.w);
            } else {
                float2 bv = *reinterpret_cast<const float2*>(&Bs[cur][k][nBase]);
                b2[0] = pk2(bv.x, bv.y);
            }
#pragma unroll
            for (int i = 0; i < 8; i++) {
                unsigned long long a2 = pk2(a[i], a[i]);
#pragma unroll
                for (int j = 0; j < NJ; j++) ffma2(acc2[i][j], a2, b2[j]);
            }
        }
        if (t + 1 < nT) storeT(1 - cur);
        __syncthreads();
    }

    if (MODE == 0) {
#pragma unroll
        for (int i = 0; i < 8; i++) {
            int r = m0 + mBase + i;
            if (r >= M) continue;
#pragma unroll
            for (int j = 0; j < NJ; j++) {
                int c = nBase + j*2;
                if (c + 1 < Ncols) {
                    float2 v = upk(acc2[i][j]);
                    v.x += bias[c]; v.y += bias[c+1];
                    *reinterpret_cast<float2*>(&C[(long)r*Ncols + c]) = v;
                } else if (c < Ncols) {
                    float2 v = upk(acc2[i][j]);
                    C[(long)r*Ncols + c] = v.x + bias[c];
                }
            }
        }
    } else {
        if (tid < BN) cs[tid] = 0.f;
        __syncthreads();
#pragma unroll
        for (int j = 0; j < NJ; j++) {
            int c = nBase + j*2;
            if (c < Ncols) {
                float b0 = bias[c];
                float b1 = (c + 1 < Ncols) ? bias[c+1] : 0.f;
                float s0 = 0.f, s1 = 0.f;
#pragma unroll
                for (int i = 0; i < 8; i++) {
                    int r = m0 + mBase + i;
                    if (r < M) {
                        float2 v = upk(acc2[i][j]);
                        s0 += tanhf(v.x + b0);
                        s1 += tanhf(v.y + b1);
                    }
                }
                atomicAdd(&cs[c], s0);
                if (c + 1 < Ncols) atomicAdd(&cs[c + 1], s1);
            }
        }
        __syncthreads();
        if (tid < BN && tid < Ncols)
            atomicAdd(&colsum[z*colsumStride + tid], cs[tid]);
    }
}

// ---------------------------------------------------------------------------
// Attention logits, layer 1: warp per (relation, node).
// Fusion: blocks with blockIdx.x >= gx (y==0) run CSR fill (grid-stride).
// ---------------------------------------------------------------------------
__global__ void k_logits1(const float* __restrict__ att_src,
                          const float* __restrict__ att_dst,
                          int gx, const int* __restrict__ fEdges)
{
    if ((int)blockIdx.x >= gx) {
        if (blockIdx.y != 0 || fEdges == nullptr) return;
        int nb = gridDim.x - gx;
        long base   = (long)((int)blockIdx.x - gx) * blockDim.x + threadIdx.x;
        long stride = (long)nb * blockDim.x;
        for (long idx = base; idx < (long)NR*NE; idx += stride) {
            int e = (int)(idx / NE), i = (int)(idx - (long)e*NE);
            int row = fEdges[(long)e*2*NE + i];
            int col = fEdges[(long)e*2*NE + NE + i];
            int pos = atomicAdd(&g_cursor[e*NN + col], 1);
            g_srcs[e*NE + pos] = row;
        }
        return;
    }

    int e = blockIdx.y;
    int n = blockIdx.x * 8 + (threadIdx.x >> 5);
    if (n >= NN) return;
    int l = threadIdx.x & 31;

    const float4* hs = reinterpret_cast<const float4*>(g_h1 + c_SRC[e]*NN*C1 + n*C1);
    const float4* hd = reinterpret_cast<const float4*>(g_h1 + c_DST[e]*NN*C1 + n*C1);
    const float4* as = reinterpret_cast<const float4*>(att_src + e*C1);
    const float4* ad = reinterpret_cast<const float4*>(att_dst + e*C1);

    float4 a = hs[l], b = as[l];
    float ps = a.x*b.x + a.y*b.y + a.z*b.z + a.w*b.w;
    float4 c = hd[l], d = ad[l];
    float pd = c.x*d.x + c.y*d.y + c.z*d.z + c.w*d.w;
    ps += __shfl_xor_sync(0xffffffffu, ps, 1);
    ps += __shfl_xor_sync(0xffffffffu, ps, 2);
    pd += __shfl_xor_sync(0xffffffffu, pd, 1);
    pd += __shfl_xor_sync(0xffffffffu, pd, 2);
    if ((l & 3) == 0) {
        g_asrc1[(e*NN + n)*H1 + (l >> 2)] = ps;
        g_adst1[(e*NN + n)*H1 + (l >> 2)] = pd;
    }
}

// ---------------------------------------------------------------------------
// Aggregation layer 1 (fused segment softmax): warp per (node, relation).
// Pass A computes per-head (m, 1/s) online (4 lanes/head, merged via shfl);
// Pass B gathers rows with inline-recomputed weights.
// ---------------------------------------------------------------------------
__global__ void k_agg1() {
    int e = blockIdx.y;
    int n = blockIdx.x * 8 + (threadIdx.x >> 5);
    if (n >= NN) return;
    int l  = threadIdx.x & 31;
    int h  = l >> 2;
    int il = l & 3;

    int off = g_offsets[e*(NN+1) + n];
    int deg = g_offsets[e*(NN+1) + n + 1] - off;
    float4* out = reinterpret_cast<float4*>(g_out1 + (long)(e*NN + n) * C1);
    if (deg == 0) { out[l] = make_float4(0.f,0.f,0.f,0.f); return; }

    const int*    sr  = g_srcs + e*NE + off;
    const float*  asr = g_asrc1 + e*NN*H1;
    const float4* hs  = reinterpret_cast<const float4*>(g_h1 + c_SRC[e]*NN*C1);
    float ad = g_adst1[(e*NN + n)*H1 + h];

    // ---- pass A: online (m, s) per head ----
    float m = -1e30f, s = 0.f;
    for (int i = il; i < deg; i += 4) {
        float a = asr[sr[i]*H1 + h] + ad;
        a = a > 0.f ? a : 0.2f * a;
        if (a > m) { s = s * __expf(m - a) + 1.f; m = a; }
        else        s += __expf(a - m);
    }
#pragma unroll
    for (int o = 1; o <= 2; o <<= 1) {
        float mo = __shfl_xor_sync(0xffffffffu, m, o);
        float so = __shfl_xor_sync(0xffffffffu, s, o);
        float mn = fmaxf(m, mo);
        s = s * __expf(m - mn) + so * __expf(mo - mn);
        m = mn;
    }
    float inv = 1.f / (s + 1e-16f);

    // ---- pass B: weighted gather ----
    float4 acc = make_float4(0.f,0.f,0.f,0.f);
    int i = 0;
    for (; i + 4 <= deg; i += 4) {
        int r0 = sr[i], r1 = sr[i+1], r2 = sr[i+2], r3 = sr[i+3];
        float a0 = asr[r0*H1 + h] + ad, a1 = asr[r1*H1 + h] + ad;
        float a2 = asr[r2*H1 + h] + ad, a3 = asr[r3*H1 + h] + ad;
        a0 = a0 > 0.f ? a0 : 0.2f*a0;  a1 = a1 > 0.f ? a1 : 0.2f*a1;
        a2 = a2 > 0.f ? a2 : 0.2f*a2;  a3 = a3 > 0.f ? a3 : 0.2f*a3;
        float w0 = __expf(a0 - m) * inv, w1 = __expf(a1 - m) * inv;
        float w2 = __expf(a2 - m) * inv, w3 = __expf(a3 - m) * inv;
        float4 v0 = hs[r0*32 + l], v1 = hs[r1*32 + l];
        float4 v2 = hs[r2*32 + l], v3 = hs[r3*32 + l];
        acc.x += w0*v0.x + w1*v1.x + w2*v2.x + w3*v3.x;
        acc.y += w0*v0.y + w1*v1.y + w2*v2.y + w3*v3.y;
        acc.z += w0*v0.z + w1*v1.z + w2*v2.z + w3*v3.z;
        acc.w += w0*v0.w + w1*v1.w + w2*v2.w + w3*v3.w;
    }
    for (; i < deg; i++) {
        int r = sr[i];
        float a = asr[r*H1 + h] + ad;
        a = a > 0.f ? a : 0.2f*a;
        float wv = __expf(a - m) * inv;
        float4 v = hs[r*32 + l];
        acc.x += wv*v.x; acc.y += wv*v.y; acc.z += wv*v.z; acc.w += wv*v.w;
    }
    out[l] = make_float4(fmaxf(acc.x,0.f), fmaxf(acc.y,0.f),
                         fmaxf(acc.z,0.f), fmaxf(acc.w,0.f));
}

// ---------------------------------------------------------------------------
// Semantic score + group softmax (tiny)
// ---------------------------------------------------------------------------
__global__ void k_score1(const float* __restrict__ q) {
    __shared__ float red[128];
    __shared__ float sc[NR];
    int t = threadIdx.x;
    for (int e = 0; e < NR; e++) {
        float p = q[t] * g_colsum1[e*C1 + t];
        red[t] = p; __syncthreads();
        for (int s = 64; s > 0; s >>= 1) {
            if (t < s) red[t] += red[t + s];
            __syncthreads();
        }
        if (t == 0) sc[e] = red[0] / (float)NN;
        __syncthreads();
    }
    if (t < NT) {
        int b = c_GRPOFF[t], e2 = c_GRPOFF[t+1];
        float m = -1e30f;
        for (int g = b; g < e2; g++) m = fmaxf(m, sc[c_GRP[g]]);
        float ssum = 0.f;
        for (int g = b; g < e2; g++) ssum += expf(sc[c_GRP[g]] - m);
        for (int g = b; g < e2; g++)
            g_sattn1[c_GRP[g]] = expf(sc[c_GRP[g]] - m) / ssum;
    }
}

__global__ void k_score2(const float* __restrict__ q) {
    __shared__ float red[128];
    __shared__ float sc[NR];
    int t = threadIdx.x;
    for (int e = 0; e < NR; e++) {
        float p = (t < C2) ? q[t] * g_colsum2[e*C2 + t] : 0.f;
        red[t] = p; __syncthreads();
        for (int s = 64; s > 0; s >>= 1) {
            if (t < s) red[t] += red[t + s];
            __syncthreads();
        }
        if (t == 0) sc[e] = red[0] / (float)NN;
        __syncthreads();
    }
    if (t < NT) {
        int b = c_GRPOFF[t], e2 = c_GRPOFF[t+1];
        float m = -1e30f;
        for (int g = b; g < e2; g++) m = fmaxf(m, sc[c_GRP[g]]);
        float ssum = 0.f;
        for (int g = b; g < e2; g++) ssum += expf(sc[c_GRP[g]] - m);
        for (int g = b; g < e2; g++)
            g_sattn2[c_GRP[g]] = expf(sc[c_GRP[g]] - m) / ssum;
    }
}

// ---------------------------------------------------------------------------
// Fuse relations per dst type (layer1) + elu -> x2
// ---------------------------------------------------------------------------
__global__ void k_combine1() {
    long idx = (long)blockIdx.x * blockDim.x + threadIdx.x;
    if (idx >= (long)NT*NN*C1) return;
    int t  = (int)(idx / (NN*C1));
    int nc = (int)(idx - (long)t*NN*C1);
    float v = 0.f;
    for (int g = c_GRPOFF[t]; g < c_GRPOFF[t+1]; g++) {
        int e = c_GRP[g];
        v += g_sattn1[e] * g_out1[(long)e*NN*C1 + nc];
    }
    g_x2[idx] = v > 0.f ? v : __expf(v) - 1.f;
}

// ---------------------------------------------------------------------------
// Layer 2 logits (H=1): warp per (relation, node)
// ---------------------------------------------------------------------------
__global__ void k_logits2(const float* __restrict__ att_src,
                          const float* __restrict__ att_dst)
{
    int e = blockIdx.y;
    int n = blockIdx.x * 8 + (threadIdx.x >> 5);
    if (n >= NN) return;
    int l = threadIdx.x & 31;
    float ps = g_h2[c_SRC[e]*NN*C2 + n*C2 + l] * att_src[e*C2 + l];
    float pd = g_h2[c_DST[e]*NN*C2 + n*C2 + l] * att_dst[e*C2 + l];
#pragma unroll
    for (int o = 16; o > 0; o >>= 1) {
        ps += __shfl_xor_sync(0xffffffffu, ps, o);
        pd += __shfl_xor_sync(0xffffffffu, pd, o);
    }
    if (l == 0) { g_asrc2[e*NN + n] = ps; g_adst2[e*NN + n] = pd; }
}

// ---------------------------------------------------------------------------
// Aggregation layer 2 (fused segment softmax): warp per (node, relation).
// Pass A: full-warp online (m, s). Pass B: 4 edges in flight, 8 lanes each.
// ---------------------------------------------------------------------------
__global__ void k_agg2() {
    int e = blockIdx.y;
    int n = blockIdx.x * 8 + (threadIdx.x >> 5);
    if (n >= NN) return;
    int l = threadIdx.x & 31;
    int g = l >> 3;                    // edge group 0..3
    int q = l & 7;                     // channel quad 0..7

    int off = g_offsets[e*(NN+1) + n];
    int deg = g_offsets[e*(NN+1) + n + 1] - off;
    float4* out = reinterpret_cast<float4*>(g_out2 + (long)(e*NN + n) * C2);
    if (deg == 0) { if (l < 8) out[q] = make_float4(0.f,0.f,0.f,0.f); return; }

    const int*    sr  = g_srcs + e*NE + off;
    const float*  asr = g_asrc2 + e*NN;
    const float4* hs  = reinterpret_cast<const float4*>(g_h2 + c_SRC[e]*NN*C2);
    float ad = g_adst2[e*NN + n];

    // ---- pass A: online (m, s) across the whole warp ----
    float m = -1e30f, s = 0.f;
    for (int i = l; i < deg; i += 32) {
        float a = asr[sr[i]] + ad;
        a = a > 0.f ? a : 0.2f * a;
        if (a > m) { s = s * __expf(m - a) + 1.f; m = a; }
        else        s += __expf(a - m);
    }
#pragma unroll
    for (int o = 1; o <= 16; o <<= 1) {
        float mo = __shfl_xor_sync(0xffffffffu, m, o);
        float so = __shfl_xor_sync(0xffffffffu, s, o);
        float mn = fmaxf(m, mo);
        s = s * __expf(m - mn) + so * __expf(mo - mn);
        m = mn;
    }
    float inv = 1.f / (s + 1e-16f);

    // ---- pass B: weighted gather ----
    float4 acc = make_float4(0.f,0.f,0.f,0.f);
    for (int i = g; i < deg; i += 4) {
        int r = sr[i];
        float a = asr[r] + ad;
        a = a > 0.f ? a : 0.2f*a;
        float wv = __expf(a - m) * inv;
        float4 v = hs[r*8 + q];
        acc.x += wv*v.x; acc.y += wv*v.y; acc.z += wv*v.z; acc.w += wv*v.w;
    }
#pragma unroll
    for (int o = 8; o <= 16; o <<= 1) {
        acc.x += __shfl_xor_sync(0xffffffffu, acc.x, o);
        acc.y += __shfl_xor_sync(0xffffffffu, acc.y, o);
        acc.z += __shfl_xor_sync(0xffffffffu, acc.z, o);
        acc.w += __shfl_xor_sync(0xffffffffu, acc.w, o);
    }
    if (l < 8)
        out[q] = make_float4(fmaxf(acc.x,0.f), fmaxf(acc.y,0.f),
                             fmaxf(acc.z,0.f), fmaxf(acc.w,0.f));
}

// ---------------------------------------------------------------------------
// Fuse relations layer 2 + final per-node channel softmax -> d_out
// ---------------------------------------------------------------------------
__global__ void k_combine2(float* __restrict__ out) {
    int g = blockIdx.x * 8 + (threadIdx.x >> 5);
    if (g >= NT*NN) return;
    int t = g / NN, n = g - t*NN;
    int c = threadIdx.x & 31;
    float v = 0.f;
    for (int gi = c_GRPOFF[t]; gi < c_GRPOFF[t+1]; gi++) {
        int e = c_GRP[gi];
        v += g_sattn2[e] * g_out2[(long)(e*NN + n)*C2 + c];
    }
    float m = v;
#pragma unroll
    for (int o = 16; o > 0; o >>= 1)
        m = fmaxf(m, __shfl_xor_sync(0xffffffffu, m, o));
    float ex = __expf(v - m);
    float s = ex;
#pragma unroll
    for (int o = 16; o > 0; o >>= 1)
        s += __shfl_xor_sync(0xffffffffu, s, o);
    out[(long)g*C2 + c] = ex / s;
}

// ---------------------------------------------------------------------------
// Host launcher
// ---------------------------------------------------------------------------
extern "C" void kernel_launch(void* const* d_in, const int* in_sizes, int n_in,
                              void* d_out, int out_size)
{
    const float* x[4] = {(const float*)d_in[0], (const float*)d_in[1],
                         (const float*)d_in[2], (const float*)d_in[3]};
    const int*   edges    = (const int*)  d_in[4];
    const float* proj1_W  = (const float*)d_in[5];
    const float* proj1_b  = (const float*)d_in[6];
    const float* att1_src = (const float*)d_in[7];
    const float* att1_dst = (const float*)d_in[8];
    const float* k1_W     = (const float*)d_in[9];
    const float* k1_b     = (const float*)d_in[10];
    const float* q1       = (const float*)d_in[11];
    const float* proj2_W  = (const float*)d_in[12];
    const float* proj2_b  = (const float*)d_in[13];
    const float* att2_src = (const float*)d_in[14];
    const float* att2_dst = (const float*)d_in[15];
    const float* k2_W     = (const float*)d_in[16];
    const float* k2_b     = (const float*)d_in[17];
    const float* q2       = (const float*)d_in[18];
    float* out = (float*)d_out;

    float *h1p, *x2p, *h2p, *out1p, *out2p, *cs1p, *cs2p;
    cudaGetSymbolAddress((void**)&h1p,   g_h1);
    cudaGetSymbolAddress((void**)&x2p,   g_x2);
    cudaGetSymbolAddress((void**)&h2p,   g_h2);
    cudaGetSymbolAddress((void**)&out1p, g_out1);
    cudaGetSymbolAddress((void**)&out2p, g_out2);
    cudaGetSymbolAddress((void**)&cs1p,  g_colsum1);
    cudaGetSymbolAddress((void**)&cs2p,  g_colsum2);

    const int MT   = (NN + 127) / 128;   // 235 row tiles
    const int CNTB = 512;                // fused count blocks
    const int FILB = 512;                // fused fill blocks
    const int LGX  = (NN + 7) / 8;       // 3750

    k_zero <<<(NR*NN + 255)/256, 256>>>();

    // fused [proj1 GEMM ∥ count]
    k_gemm<128,0><<<dim3(MT + CNTB, 1, NT), 256>>>(
        x[0], x[1], x[2], x[3],
        proj1_W, proj1_b, h1p, NN, C1, IN1,
        0, (long)IN1*C1, C1, (long)NN*C1, nullptr, 0,
        MT, edges);

    k_scan <<<NR, 1024>>>();

    // fused [logits1 ∥ fill]
    k_logits1<<<dim3(LGX + FILB, NR), 256>>>(att1_src, att1_dst, LGX, edges);

    // fused [softmax + aggregation]
    k_agg1<<<dim3(LGX, NR), 256>>>();

    k_gemm<128,1><<<dim3(MT, 1, NR), 256>>>(
        out1p, nullptr, nullptr, nullptr,
        k1_W, k1_b, nullptr, NN, C1, C1,
        (long)NN*C1, 0, 0, 0, cs1p, C1,
        MT, nullptr);
    k_score1<<<1, 128>>>(q1);
    k_combine1<<<((long)NT*NN*C1 + 255)/256, 256>>>();

    // ---- layer 2 projections, batched z=4, BN=32 ----
    k_gemm<32,0><<<dim3(MT, 1, NT), 256>>>(
        x2p, nullptr, nullptr, nullptr,
        proj2_W, proj2_b, h2p, NN, C2, C1,
        (long)NN*C1, (long)C1*C2, C2, (long)NN*C2, nullptr, 0,
        MT, nullptr);

    k_logits2<<<dim3(LGX, NR), 256>>>(att2_src, att2_dst);
    k_agg2   <<<dim3(LGX, NR), 256>>>();

    k_gemm<32,1><<<dim3(MT, 1, NR), 256>>>(
        out2p, nullptr, nullptr, nullptr,
        k2_W, k2_b, nullptr, NN, C2, C2,
        (long)NN*C2, 0, 0, 0, cs2p, C2,
        MT, nullptr);
    k_score2<<<1, 128>>>(q2);

    k_combine2<<<(NT*NN + 7)/8, 256>>>(out);
}

// round 14
// speedup vs baseline: 1.1846x; 1.0770x over previous
#include <cuda_runtime.h>
#include <cuda_fp16.h>
#include <math.h>

// ---------------------------------------------------------------------------
// Problem constants
// ---------------------------------------------------------------------------
constexpr int NN  = 30000;    // nodes per type
constexpr int NE  = 400000;   // edges per relation
constexpr int NR  = 10;       // relations
constexpr int NT  = 4;        // node types
constexpr int C1  = 128;      // layer1 channels
constexpr int H1  = 8;        // layer1 heads
constexpr int IN1 = 256;      // layer1 input dim
constexpr int C2  = 32;       // layer2 channels

__constant__ int c_SRC[NR]    = {0,1,2,3,0,1,2,1,3,1};
__constant__ int c_DST[NR]    = {0,1,2,3,1,0,1,2,1,3};
__constant__ int c_GRPOFF[5]  = {0,2,6,8,10};
__constant__ int c_GRP[NR]    = {0,5, 1,4,6,8, 2,7, 3,9};

// ---------------------------------------------------------------------------
// Scratch (static device arrays: allocation-free)
// ---------------------------------------------------------------------------
__device__ __align__(16) float g_h1   [NT*NN*C1];
__device__ __align__(16) __half g_h1h [NT*NN*C1];   // fp16 gather copy
__device__ __align__(16) float g_asrc1[NR*NN*H1];
__device__ __align__(16) float g_adst1[NR*NN*H1];
__device__ __align__(16) float g_out1 [NR*NN*C1];
__device__ __align__(16) float g_x2   [NT*NN*C1];
__device__ __align__(16) float g_h2   [NT*NN*C2];
__device__ __align__(16) __half g_h2h [NT*NN*C2];   // fp16 gather copy
__device__ __align__(16) float g_asrc2[NR*NN];
__device__ __align__(16) float g_adst2[NR*NN];
__device__ __align__(16) float g_out2 [NR*NN*C2];
__device__ float g_colsum1[NR*C1];
__device__ float g_colsum2[NR*C2];
__device__ float g_sattn1[NR];
__device__ float g_sattn2[NR];
__device__ int   g_counts [NR*NN];
__device__ int   g_offsets[NR*(NN+1)];
__device__ int   g_cursor [NR*NN];
__device__ int   g_srcs   [NR*NE];

// ---------------------------------------------------------------------------
// Packed f32x2 helpers (FFMA2)
// ---------------------------------------------------------------------------
__device__ __forceinline__ void ffma2(unsigned long long& c,
                                      unsigned long long a,
                                      unsigned long long b) {
    asm("fma.rn.f32x2 %0, %1, %2, %0;" : "+l"(c) : "l"(a), "l"(b));
}
__device__ __forceinline__ unsigned long long pk2(float x, float y) {
    unsigned long long r;
    asm("mov.b64 %0, {%1, %2};" : "=l"(r) : "f"(x), "f"(y));
    return r;
}
__device__ __forceinline__ float2 upk(unsigned long long v) {
    float2 r;
    asm("mov.b64 {%0, %1}, %2;" : "=f"(r.x), "=f"(r.y) : "l"(v));
    return r;
}

// ---------------------------------------------------------------------------
// Zeroing
// ---------------------------------------------------------------------------
__global__ void k_zero() {
    int i = blockIdx.x * blockDim.x + threadIdx.x;
    if (i < NR*NN) g_counts[i] = 0;
    if (i < NR*C1) g_colsum1[i] = 0.f;
    if (i < NR*C2) g_colsum2[i] = 0.f;
}

// ---------------------------------------------------------------------------
// CSR scan: one block (1024 threads) per relation
// ---------------------------------------------------------------------------
__global__ void k_scan() {
    const int e = blockIdx.x;
    const int t = threadIdx.x;
    constexpr int CH = 30;
    int base = t * CH;
    int cnt[CH];
    int sum = 0;
#pragma unroll
    for (int i = 0; i < CH; i++) {
        int idx = base + i;
        int v = (idx < NN) ? g_counts[e*NN + idx] : 0;
        cnt[i] = v; sum += v;
    }
    __shared__ int s[1024];
    s[t] = sum; __syncthreads();
    for (int d = 1; d < 1024; d <<= 1) {
        int v = (t >= d) ? s[t-d] : 0;
        __syncthreads();
        s[t] += v;
        __syncthreads();
    }
    int run = s[t] - sum;
#pragma unroll
    for (int i = 0; i < CH; i++) {
        int idx = base + i;
        if (idx < NN) {
            g_offsets[e*(NN+1) + idx] = run;
            g_cursor [e*NN + idx]     = run;
            run += cnt[i];
        }
    }
    if (t == 1023) g_offsets[e*(NN+1) + NN] = s[1023];
}

// ---------------------------------------------------------------------------
// fp32 GEMM (FFMA2 mainloop, double-buffered smem, one sync per tile).
// MODE 0: C = acc + bias (plus optional fp16 copy Chalf).
// MODE 1: colsum[col] += sum_rows tanh(acc + bias).
// Fusion: blocks with blockIdx.x >= gemmGridX (z==0) run CSR edge counting.
// ---------------------------------------------------------------------------
template <int BN, int MODE>
__global__ void __launch_bounds__(256)
k_gemm(const float* __restrict__ A0, const float* __restrict__ A1,
       const float* __restrict__ A2, const float* __restrict__ A3,
       const float* __restrict__ B,
       const float* __restrict__ bias, float* __restrict__ C,
       __half* __restrict__ Chalf,
       int M, int Ncols, int K, long strideA, long strideB, long strideBias,
       long strideC, float* __restrict__ colsum, int colsumStride,
       int gemmGridX, const int* __restrict__ cEdges)
{
    constexpr int BM = 128, BK = 16;
    constexpr int NJ = (BN == 128) ? 4 : 1;
    __shared__ float As[2][BK][BM];
    __shared__ float Bs[2][BK][BN];
    __shared__ float cs[BN];

    // ---- fused count role ----
    if ((int)blockIdx.x >= gemmGridX) {
        if (blockIdx.z != 0 || cEdges == nullptr) return;
        int nb = gridDim.x - gemmGridX;
        long base   = (long)((int)blockIdx.x - gemmGridX) * blockDim.x + threadIdx.x;
        long stride = (long)nb * blockDim.x;
        for (long idx = base; idx < (long)NR*NE; idx += stride) {
            int e = (int)(idx / NE), i = (int)(idx - (long)e*NE);
            int col = cEdges[(long)e*2*NE + NE + i];
            atomicAdd(&g_counts[e*NN + col], 1);
        }
        return;
    }

    const int z = blockIdx.z;
    const float* A = strideA ? (A0 + (long)z * strideA)
                             : (z == 0 ? A0 : z == 1 ? A1 : z == 2 ? A2 : A3);
    B    += (long)z * strideB;
    bias += (long)z * strideBias;
    if (MODE == 0) {
        C += (long)z * strideC;
        if (Chalf) Chalf += (long)z * strideC;
    }

    const int m0 = blockIdx.x * BM;
    const int tid  = threadIdx.x;
    int mBase, nBase;
    if (BN == 128) {
        const int wid  = tid >> 5, lane = tid & 31;
        mBase = (wid >> 2)*64 + (lane >> 2)*8;
        nBase = (wid & 3)*32 + (lane & 3)*8;
    } else {
        mBase = (tid >> 4) * 8;
        nBase = (tid & 15) * 2;
    }

    unsigned long long acc2[8][NJ];
#pragma unroll
    for (int i = 0; i < 8; i++)
#pragma unroll
        for (int j = 0; j < NJ; j++) acc2[i][j] = 0ull;

    const int am = tid >> 1, akq = (tid & 1) * 2;   // A: row, float4-pair idx
    const float4 zero4 = make_float4(0.f,0.f,0.f,0.f);
    float4 pa[2], pb[2];

    auto loadA = [&](int k0) {
        pa[0] = zero4; pa[1] = zero4;
        if (m0 + am < M) {
            const float4* src = reinterpret_cast<const float4*>(
                A + (long)(m0 + am)*K + k0 + akq*4);
            pa[0] = src[0]; pa[1] = src[1];
        }
    };
    auto loadB = [&](int k0) {
        if (BN == 128) {
#pragma unroll
            for (int it = 0; it < 2; it++) {
                int lin = tid + it * 256;
                int k = lin >> 5, nq = lin & 31;
                pb[it] = zero4;
                if (nq*4 + 3 < Ncols)
                    pb[it] = *reinterpret_cast<const float4*>(
                        B + (long)(k0+k)*Ncols + nq*4);
            }
        } else {
            if (tid < 128) {
                int k = tid >> 3, nq = tid & 7;
                pb[0] = zero4;
                if (nq*4 + 3 < Ncols)
                    pb[0] = *reinterpret_cast<const float4*>(
                        B + (long)(k0+k)*Ncols + nq*4);
            }
        }
    };
    auto storeT = [&](int buf) {
        As[buf][akq*4+0][am] = pa[0].x; As[buf][akq*4+1][am] = pa[0].y;
        As[buf][akq*4+2][am] = pa[0].z; As[buf][akq*4+3][am] = pa[0].w;
        As[buf][akq*4+4][am] = pa[1].x; As[buf][akq*4+5][am] = pa[1].y;
        As[buf][akq*4+6][am] = pa[1].z; As[buf][akq*4+7][am] = pa[1].w;
        if (BN == 128) {
#pragma unroll
            for (int it = 0; it < 2; it++) {
                int lin = tid + it * 256;
                int k = lin >> 5, nq = lin & 31;
                *reinterpret_cast<float4*>(&Bs[buf][k][nq*4]) = pb[it];
            }
        } else {
            if (tid < 128) {
                int k = tid >> 3, nq = tid & 7;
                *reinterpret_cast<float4*>(&Bs[buf][k][nq*4]) = pb[0];
            }
        }
    };

    const int nT = K / BK;
    loadA(0); loadB(0);
    storeT(0);
    __syncthreads();

    for (int t = 0; t < nT; t++) {
        int cur = t & 1;
        if (t + 1 < nT) { loadA((t+1)*BK); loadB((t+1)*BK); }
#pragma unroll
        for (int k = 0; k < BK; k++) {
            const float4* ap4 = reinterpret_cast<const float4*>(&As[cur][k][mBase]);
            float4 av0 = ap4[0], av1 = ap4[1];
            float a[8] = {av0.x, av0.y, av0.z, av0.w,
                          av1.x, av1.y, av1.z, av1.w};
            unsigned long long b2[NJ];
            if (BN == 128) {
                const float4* bp4 = reinterpret_cast<const float4*>(&Bs[cur][k][nBase]);
                float4 bv0 = bp4[0], bv1 = bp4[1];
                b2[0] = pk2(bv0.x, bv0.y);
                b2[1] = pk2(bv0.z, bv0.w);
                b2[2 % NJ] = pk2(bv1.x, bv1.y);
                b2[3 % NJ] = pk2(bv1.z, bv1.w);
            } else {
                float2 bv = *reinterpret_cast<const float2*>(&Bs[cur][k][nBase]);
                b2[0] = pk2(bv.x, bv.y);
            }
#pragma unroll
            for (int i = 0; i < 8; i++) {
                unsigned long long a2 = pk2(a[i], a[i]);
#pragma unroll
                for (int j = 0; j < NJ; j++) ffma2(acc2[i][j], a2, b2[j]);
            }
        }
        if (t + 1 < nT) storeT(1 - cur);
        __syncthreads();
    }

    if (MODE == 0) {
#pragma unroll
        for (int i = 0; i < 8; i++) {
            int r = m0 + mBase + i;
            if (r >= M) continue;
#pragma unroll
            for (int j = 0; j < NJ; j++) {
                int c = nBase + j*2;
                if (c + 1 < Ncols) {
                    float2 v = upk(acc2[i][j]);
                    v.x += bias[c]; v.y += bias[c+1];
                    *reinterpret_cast<float2*>(&C[(long)r*Ncols + c]) = v;
                    if (Chalf)
                        *reinterpret_cast<__half2*>(&Chalf[(long)r*Ncols + c]) =
                            __floats2half2_rn(v.x, v.y);
                } else if (c < Ncols) {
                    float2 v = upk(acc2[i][j]);
                    C[(long)r*Ncols + c] = v.x + bias[c];
                    if (Chalf) Chalf[(long)r*Ncols + c] = __float2half(v.x + bias[c]);
                }
            }
        }
    } else {
        if (tid < BN) cs[tid] = 0.f;
        __syncthreads();
#pragma unroll
        for (int j = 0; j < NJ; j++) {
            int c = nBase + j*2;
            if (c < Ncols) {
                float b0 = bias[c];
                float b1 = (c + 1 < Ncols) ? bias[c+1] : 0.f;
                float s0 = 0.f, s1 = 0.f;
#pragma unroll
                for (int i = 0; i < 8; i++) {
                    int r = m0 + mBase + i;
                    if (r < M) {
                        float2 v = upk(acc2[i][j]);
                        s0 += tanhf(v.x + b0);
                        s1 += tanhf(v.y + b1);
                    }
                }
                atomicAdd(&cs[c], s0);
                if (c + 1 < Ncols) atomicAdd(&cs[c + 1], s1);
            }
        }
        __syncthreads();
        if (tid < BN && tid < Ncols)
            atomicAdd(&colsum[z*colsumStride + tid], cs[tid]);
    }
}

// ---------------------------------------------------------------------------
// Attention logits, layer 1: warp per (relation, node).
// Fusion: blocks with blockIdx.x >= gx (y==0) run CSR fill (grid-stride).
// ---------------------------------------------------------------------------
__global__ void k_logits1(const float* __restrict__ att_src,
                          const float* __restrict__ att_dst,
                          int gx, const int* __restrict__ fEdges)
{
    if ((int)blockIdx.x >= gx) {
        if (blockIdx.y != 0 || fEdges == nullptr) return;
        int nb = gridDim.x - gx;
        long base   = (long)((int)blockIdx.x - gx) * blockDim.x + threadIdx.x;
        long stride = (long)nb * blockDim.x;
        for (long idx = base; idx < (long)NR*NE; idx += stride) {
            int e = (int)(idx / NE), i = (int)(idx - (long)e*NE);
            int row = fEdges[(long)e*2*NE + i];
            int col = fEdges[(long)e*2*NE + NE + i];
            int pos = atomicAdd(&g_cursor[e*NN + col], 1);
            g_srcs[e*NE + pos] = row;
        }
        return;
    }

    int e = blockIdx.y;
    int n = blockIdx.x * 8 + (threadIdx.x >> 5);
    if (n >= NN) return;
    int l = threadIdx.x & 31;

    const float4* hs = reinterpret_cast<const float4*>(g_h1 + c_SRC[e]*NN*C1 + n*C1);
    const float4* hd = reinterpret_cast<const float4*>(g_h1 + c_DST[e]*NN*C1 + n*C1);
    const float4* as = reinterpret_cast<const float4*>(att_src + e*C1);
    const float4* ad = reinterpret_cast<const float4*>(att_dst + e*C1);

    float4 a = hs[l], b = as[l];
    float ps = a.x*b.x + a.y*b.y + a.z*b.z + a.w*b.w;
    float4 c = hd[l], d = ad[l];
    float pd = c.x*d.x + c.y*d.y + c.z*d.z + c.w*d.w;
    ps += __shfl_xor_sync(0xffffffffu, ps, 1);
    ps += __shfl_xor_sync(0xffffffffu, ps, 2);
    pd += __shfl_xor_sync(0xffffffffu, pd, 1);
    pd += __shfl_xor_sync(0xffffffffu, pd, 2);
    if ((l & 3) == 0) {
        g_asrc1[(e*NN + n)*H1 + (l >> 2)] = ps;
        g_adst1[(e*NN + n)*H1 + (l >> 2)] = pd;
    }
}

// ---------------------------------------------------------------------------
// Aggregation layer 1 (fused segment softmax): warp per (node, relation).
// Pass A: per-head (m, 1/s) online. Pass B: fp16 row gathers (half traffic).
// ---------------------------------------------------------------------------
__global__ void k_agg1() {
    int e = blockIdx.y;
    int n = blockIdx.x * 8 + (threadIdx.x >> 5);
    if (n >= NN) return;
    int l  = threadIdx.x & 31;
    int h  = l >> 2;
    int il = l & 3;

    int off = g_offsets[e*(NN+1) + n];
    int deg = g_offsets[e*(NN+1) + n + 1] - off;
    float4* out = reinterpret_cast<float4*>(g_out1 + (long)(e*NN + n) * C1);
    if (deg == 0) { out[l] = make_float4(0.f,0.f,0.f,0.f); return; }

    const int*   sr  = g_srcs + e*NE + off;
    const float* asr = g_asrc1 + e*NN*H1;
    const uint2* hs  = reinterpret_cast<const uint2*>(g_h1h + (long)c_SRC[e]*NN*C1);
    float ad = g_adst1[(e*NN + n)*H1 + h];

    // ---- pass A: online (m, s) per head ----
    float m = -1e30f, s = 0.f;
    for (int i = il; i < deg; i += 4) {
        float a = asr[sr[i]*H1 + h] + ad;
        a = a > 0.f ? a : 0.2f * a;
        if (a > m) { s = s * __expf(m - a) + 1.f; m = a; }
        else        s += __expf(a - m);
    }
#pragma unroll
    for (int o = 1; o <= 2; o <<= 1) {
        float mo = __shfl_xor_sync(0xffffffffu, m, o);
        float so = __shfl_xor_sync(0xffffffffu, s, o);
        float mn = fmaxf(m, mo);
        s = s * __expf(m - mn) + so * __expf(mo - mn);
        m = mn;
    }
    float inv = 1.f / (s + 1e-16f);

    // ---- pass B: weighted gather (fp16 rows, fp32 accumulate) ----
    float4 acc = make_float4(0.f,0.f,0.f,0.f);
    int i = 0;
    for (; i + 4 <= deg; i += 4) {
        int r0 = sr[i], r1 = sr[i+1], r2 = sr[i+2], r3 = sr[i+3];
        float a0 = asr[r0*H1 + h] + ad, a1 = asr[r1*H1 + h] + ad;
        float a2 = asr[r2*H1 + h] + ad, a3 = asr[r3*H1 + h] + ad;
        a0 = a0 > 0.f ? a0 : 0.2f*a0;  a1 = a1 > 0.f ? a1 : 0.2f*a1;
        a2 = a2 > 0.f ? a2 : 0.2f*a2;  a3 = a3 > 0.f ? a3 : 0.2f*a3;
        float w0 = __expf(a0 - m) * inv, w1 = __expf(a1 - m) * inv;
        float w2 = __expf(a2 - m) * inv, w3 = __expf(a3 - m) * inv;
        uint2 u0 = hs[r0*32 + l], u1 = hs[r1*32 + l];
        uint2 u2 = hs[r2*32 + l], u3 = hs[r3*32 + l];
        float2 p0a = __half22float2(*reinterpret_cast<__half2*>(&u0.x));
        float2 p0b = __half22float2(*reinterpret_cast<__half2*>(&u0.y));
        float2 p1a = __half22float2(*reinterpret_cast<__half2*>(&u1.x));
        float2 p1b = __half22float2(*reinterpret_cast<__half2*>(&u1.y));
        float2 p2a = __half22float2(*reinterpret_cast<__half2*>(&u2.x));
        float2 p2b = __half22float2(*reinterpret_cast<__half2*>(&u2.y));
        float2 p3a = __half22float2(*reinterpret_cast<__half2*>(&u3.x));
        float2 p3b = __half22float2(*reinterpret_cast<__half2*>(&u3.y));
        acc.x += w0*p0a.x + w1*p1a.x + w2*p2a.x + w3*p3a.x;
        acc.y += w0*p0a.y + w1*p1a.y + w2*p2a.y + w3*p3a.y;
        acc.z += w0*p0b.x + w1*p1b.x + w2*p2b.x + w3*p3b.x;
        acc.w += w0*p0b.y + w1*p1b.y + w2*p2b.y + w3*p3b.y;
    }
    for (; i < deg; i++) {
        int r = sr[i];
        float a = asr[r*H1 + h] + ad;
        a = a > 0.f ? a : 0.2f*a;
        float wv = __expf(a - m) * inv;
        uint2 u = hs[r*32 + l];
        float2 pa = __half22float2(*reinterpret_cast<__half2*>(&u.x));
        float2 pb = __half22float2(*reinterpret_cast<__half2*>(&u.y));
        acc.x += wv*pa.x; acc.y += wv*pa.y; acc.z += wv*pb.x; acc.w += wv*pb.y;
    }
    out[l] = make_float4(fmaxf(acc.x,0.f), fmaxf(acc.y,0.f),
                         fmaxf(acc.z,0.f), fmaxf(acc.w,0.f));
}

// ---------------------------------------------------------------------------
// Semantic score + group softmax (tiny)
// ---------------------------------------------------------------------------
__global__ void k_score1(const float* __restrict__ q) {
    __shared__ float red[128];
    __shared__ float sc[NR];
    int t = threadIdx.x;
    for (int e = 0; e < NR; e++) {
        float p = q[t] * g_colsum1[e*C1 + t];
        red[t] = p; __syncthreads();
        for (int s = 64; s > 0; s >>= 1) {
            if (t < s) red[t] += red[t + s];
            __syncthreads();
        }
        if (t == 0) sc[e] = red[0] / (float)NN;
        __syncthreads();
    }
    if (t < NT) {
        int b = c_GRPOFF[t], e2 = c_GRPOFF[t+1];
        float m = -1e30f;
        for (int g = b; g < e2; g++) m = fmaxf(m, sc[c_GRP[g]]);
        float ssum = 0.f;
        for (int g = b; g < e2; g++) ssum += expf(sc[c_GRP[g]] - m);
        for (int g = b; g < e2; g++)
            g_sattn1[c_GRP[g]] = expf(sc[c_GRP[g]] - m) / ssum;
    }
}

__global__ void k_score2(const float* __restrict__ q) {
    __shared__ float red[128];
    __shared__ float sc[NR];
    int t = threadIdx.x;
    for (int e = 0; e < NR; e++) {
        float p = (t < C2) ? q[t] * g_colsum2[e*C2 + t] : 0.f;
        red[t] = p; __syncthreads();
        for (int s = 64; s > 0; s >>= 1) {
            if (t < s) red[t] += red[t + s];
            __syncthreads();
        }
        if (t == 0) sc[e] = red[0] / (float)NN;
        __syncthreads();
    }
    if (t < NT) {
        int b = c_GRPOFF[t], e2 = c_GRPOFF[t+1];
        float m = -1e30f;
        for (int g = b; g < e2; g++) m = fmaxf(m, sc[c_GRP[g]]);
        float ssum = 0.f;
        for (int g = b; g < e2; g++) ssum += expf(sc[c_GRP[g]] - m);
        for (int g = b; g < e2; g++)
            g_sattn2[c_GRP[g]] = expf(sc[c_GRP[g]] - m) / ssum;
    }
}

// ---------------------------------------------------------------------------
// Fuse relations per dst type (layer1) + elu -> x2
// ---------------------------------------------------------------------------
__global__ void k_combine1() {
    long idx = (long)blockIdx.x * blockDim.x + threadIdx.x;
    if (idx >= (long)NT*NN*C1) return;
    int t  = (int)(idx / (NN*C1));
    int nc = (int)(idx - (long)t*NN*C1);
    float v = 0.f;
    for (int g = c_GRPOFF[t]; g < c_GRPOFF[t+1]; g++) {
        int e = c_GRP[g];
        v += g_sattn1[e] * g_out1[(long)e*NN*C1 + nc];
    }
    g_x2[idx] = v > 0.f ? v : __expf(v) - 1.f;
}

// ---------------------------------------------------------------------------
// Layer 2 logits (H=1): warp per (relation, node)
// ---------------------------------------------------------------------------
__global__ void k_logits2(const float* __restrict__ att_src,
                          const float* __restrict__ att_dst)
{
    int e = blockIdx.y;
    int n = blockIdx.x * 8 + (threadIdx.x >> 5);
    if (n >= NN) return;
    int l = threadIdx.x & 31;
    float ps = g_h2[c_SRC[e]*NN*C2 + n*C2 + l] * att_src[e*C2 + l];
    float pd = g_h2[c_DST[e]*NN*C2 + n*C2 + l] * att_dst[e*C2 + l];
#pragma unroll
    for (int o = 16; o > 0; o >>= 1) {
        ps += __shfl_xor_sync(0xffffffffu, ps, o);
        pd += __shfl_xor_sync(0xffffffffu, pd, o);
    }
    if (l == 0) { g_asrc2[e*NN + n] = ps; g_adst2[e*NN + n] = pd; }
}

// ---------------------------------------------------------------------------
// Aggregation layer 2 (fused segment softmax): warp per (node, relation).
// Pass A: full-warp online (m, s). Pass B: fp16 gathers, 4 edges in flight.
// ---------------------------------------------------------------------------
__global__ void k_agg2() {
    int e = blockIdx.y;
    int n = blockIdx.x * 8 + (threadIdx.x >> 5);
    if (n >= NN) return;
    int l = threadIdx.x & 31;
    int g = l >> 3;                    // edge group 0..3
    int q = l & 7;                     // channel quad 0..7

    int off = g_offsets[e*(NN+1) + n];
    int deg = g_offsets[e*(NN+1) + n + 1] - off;
    float4* out = reinterpret_cast<float4*>(g_out2 + (long)(e*NN + n) * C2);
    if (deg == 0) { if (l < 8) out[q] = make_float4(0.f,0.f,0.f,0.f); return; }

    const int*   sr  = g_srcs + e*NE + off;
    const float* asr = g_asrc2 + e*NN;
    const uint2* hs  = reinterpret_cast<const uint2*>(g_h2h + (long)c_SRC[e]*NN*C2);
    float ad = g_adst2[e*NN + n];

    // ---- pass A: online (m, s) across the whole warp ----
    float m = -1e30f, s = 0.f;
    for (int i = l; i < deg; i += 32) {
        float a = asr[sr[i]] + ad;
        a = a > 0.f ? a : 0.2f * a;
        if (a > m) { s = s * __expf(m - a) + 1.f; m = a; }
        else        s += __expf(a - m);
    }
#pragma unroll
    for (int o = 1; o <= 16; o <<= 1) {
        float mo = __shfl_xor_sync(0xffffffffu, m, o);
        float so = __shfl_xor_sync(0xffffffffu, s, o);
        float mn = fmaxf(m, mo);
        s = s * __expf(m - mn) + so * __expf(mo - mn);
        m = mn;
    }
    float inv = 1.f / (s + 1e-16f);

    // ---- pass B: weighted gather (fp16 rows) ----
    float4 acc = make_float4(0.f,0.f,0.f,0.f);
    for (int i = g; i < deg; i += 4) {
        int r = sr[i];
        float a = asr[r] + ad;
        a = a > 0.f ? a : 0.2f*a;
        float wv = __expf(a - m) * inv;
        uint2 u = hs[r*8 + q];
        float2 pa = __half22float2(*reinterpret_cast<__half2*>(&u.x));
        float2 pb = __half22float2(*reinterpret_cast<__half2*>(&u.y));
        acc.x += wv*pa.x; acc.y += wv*pa.y; acc.z += wv*pb.x; acc.w += wv*pb.y;
    }
#pragma unroll
    for (int o = 8; o <= 16; o <<= 1) {
        acc.x += __shfl_xor_sync(0xffffffffu, acc.x, o);
        acc.y += __shfl_xor_sync(0xffffffffu, acc.y, o);
        acc.z += __shfl_xor_sync(0xffffffffu, acc.z, o);
        acc.w += __shfl_xor_sync(0xffffffffu, acc.w, o);
    }
    if (l < 8)
        out[q] = make_float4(fmaxf(acc.x,0.f), fmaxf(acc.y,0.f),
                             fmaxf(acc.z,0.f), fmaxf(acc.w,0.f));
}

// ---------------------------------------------------------------------------
// Fuse relations layer 2 + final per-node channel softmax -> d_out
// ---------------------------------------------------------------------------
__global__ void k_combine2(float* __restrict__ out) {
    int g = blockIdx.x * 8 + (threadIdx.x >> 5);
    if (g >= NT*NN) return;
    int t = g / NN, n = g - t*NN;
    int c = threadIdx.x & 31;
    float v = 0.f;
    for (int gi = c_GRPOFF[t]; gi < c_GRPOFF[t+1]; gi++) {
        int e = c_GRP[gi];
        v += g_sattn2[e] * g_out2[(long)(e*NN + n)*C2 + c];
    }
    float m = v;
#pragma unroll
    for (int o = 16; o > 0; o >>= 1)
        m = fmaxf(m, __shfl_xor_sync(0xffffffffu, m, o));
    float ex = __expf(v - m);
    float s = ex;
#pragma unroll
    for (int o = 16; o > 0; o >>= 1)
        s += __shfl_xor_sync(0xffffffffu, s, o);
    out[(long)g*C2 + c] = ex / s;
}

// ---------------------------------------------------------------------------
// Host launcher
// ---------------------------------------------------------------------------
extern "C" void kernel_launch(void* const* d_in, const int* in_sizes, int n_in,
                              void* d_out, int out_size)
{
    const float* x[4] = {(const float*)d_in[0], (const float*)d_in[1],
                         (const float*)d_in[2], (const float*)d_in[3]};
    const int*   edges    = (const int*)  d_in[4];
    const float* proj1_W  = (const float*)d_in[5];
    const float* proj1_b  = (const float*)d_in[6];
    const float* att1_src = (const float*)d_in[7];
    const float* att1_dst = (const float*)d_in[8];
    const float* k1_W     = (const float*)d_in[9];
    const float* k1_b     = (const float*)d_in[10];
    const float* q1       = (const float*)d_in[11];
    const float* proj2_W  = (const float*)d_in[12];
    const float* proj2_b  = (const float*)d_in[13];
    const float* att2_src = (const float*)d_in[14];
    const float* att2_dst = (const float*)d_in[15];
    const float* k2_W     = (const float*)d_in[16];
    const float* k2_b     = (const float*)d_in[17];
    const float* q2       = (const float*)d_in[18];
    float* out = (float*)d_out;

    float *h1p, *x2p, *h2p, *out1p, *out2p, *cs1p, *cs2p;
    __half *h1hp, *h2hp;
    cudaGetSymbolAddress((void**)&h1p,   g_h1);
    cudaGetSymbolAddress((void**)&h1hp,  g_h1h);
    cudaGetSymbolAddress((void**)&x2p,   g_x2);
    cudaGetSymbolAddress((void**)&h2p,   g_h2);
    cudaGetSymbolAddress((void**)&h2hp,  g_h2h);
    cudaGetSymbolAddress((void**)&out1p, g_out1);
    cudaGetSymbolAddress((void**)&out2p, g_out2);
    cudaGetSymbolAddress((void**)&cs1p,  g_colsum1);
    cudaGetSymbolAddress((void**)&cs2p,  g_colsum2);

    const int MT   = (NN + 127) / 128;   // 235 row tiles
    const int CNTB = 512;                // fused count blocks
    const int FILB = 512;                // fused fill blocks
    const int LGX  = (NN + 7) / 8;       // 3750

    k_zero <<<(NR*NN + 255)/256, 256>>>();

    // fused [proj1 GEMM ∥ count]; writes fp32 h1 + fp16 copy
    k_gemm<128,0><<<dim3(MT + CNTB, 1, NT), 256>>>(
        x[0], x[1], x[2], x[3],
        proj1_W, proj1_b, h1p, h1hp, NN, C1, IN1,
        0, (long)IN1*C1, C1, (long)NN*C1, nullptr, 0,
        MT, edges);

    k_scan <<<NR, 1024>>>();

    // fused [logits1 ∥ fill]
    k_logits1<<<dim3(LGX + FILB, NR), 256>>>(att1_src, att1_dst, LGX, edges);

    // fused [softmax + aggregation], fp16 gathers
    k_agg1<<<dim3(LGX, NR), 256>>>();

    k_gemm<128,1><<<dim3(MT, 1, NR), 256>>>(
        out1p, nullptr, nullptr, nullptr,
        k1_W, k1_b, nullptr, nullptr, NN, C1, C1,
        (long)NN*C1, 0, 0, 0, cs1p, C1,
        MT, nullptr);
    k_score1<<<1, 128>>>(q1);
    k_combine1<<<((long)NT*NN*C1 + 255)/256, 256>>>();

    // ---- layer 2 projections, batched z=4, BN=32; writes fp32 + fp16 h2 ----
    k_gemm<32,0><<<dim3(MT, 1, NT), 256>>>(
        x2p, nullptr, nullptr, nullptr,
        proj2_W, proj2_b, h2p, h2hp, NN, C2, C1,
        (long)NN*C1, (long)C1*C2, C2, (long)NN*C2, nullptr, 0,
        MT, nullptr);

    k_logits2<<<dim3(LGX, NR), 256>>>(att2_src, att2_dst);
    k_agg2   <<<dim3(LGX, NR), 256>>>();

    k_gemm<32,1><<<dim3(MT, 1, NR), 256>>>(
        out2p, nullptr, nullptr, nullptr,
        k2_W, k2_b, nullptr, nullptr, NN, C2, C2,
        (long)NN*C2, 0, 0, 0, cs2p, C2,
        MT, nullptr);
    k_score2<<<1, 128>>>(q2);

    k_combine2<<<(NT*NN + 7)/8, 256>>>(out);
}